// round 8
// baseline (speedup 1.0000x reference)
#include <cuda_runtime.h>
#include <cstdint>

// Problem constants
#define B_ROWS 8192
#define KDIM   2304     // 48*48
#define NDIM   128      // EMB_DIM
#define TM     32       // batch rows per CTA  -> 64 diff rows (32 ap + 32 an)
#define KC     32       // K chunk
#define NCHUNK (KDIM / KC)   // 72
#define ALPHA  0.2f

// Padded smem strides (in 4-byte words) for conflict-free fragment loads
#define SA_STRIDE 36    // 36%32==4  -> bank = 4*row + col  (distinct per lane in frag load)
#define SB_STRIDE 136   // 136%32==8 -> bank = 8*krow + ncol (distinct per lane in frag load)

// Round-to-nearest tf32 conversion. REQUIRED: the HMMA-tf32 datapath truncates
// raw fp32 mantissas, and truncation bias accumulates systematically in the
// final mean (measured: 1.4e-3 rel_err without this, 5.8e-6 with it).
__device__ __forceinline__ uint32_t f2tf32(float x) {
    uint32_t y;
    asm volatile("cvt.rna.tf32.f32 %0, %1;" : "=r"(y) : "f"(x));
    return y;
}

__device__ __forceinline__ void mma_tf32(float c[4], const uint32_t a[4], const uint32_t b[2]) {
    asm volatile(
        "mma.sync.aligned.m16n8k8.row.col.f32.tf32.tf32.f32 "
        "{%0,%1,%2,%3}, {%4,%5,%6,%7}, {%8,%9}, {%0,%1,%2,%3};"
        : "+f"(c[0]), "+f"(c[1]), "+f"(c[2]), "+f"(c[3])
        : "r"(a[0]), "r"(a[1]), "r"(a[2]), "r"(a[3]), "r"(b[0]), "r"(b[1]));
}

__global__ void zero_out_kernel(float* out) { out[0] = 0.0f; }

__global__ __launch_bounds__(256, 2)
void triplet_kernel(const float* __restrict__ gA,
                    const float* __restrict__ gP,
                    const float* __restrict__ gN,
                    const float* __restrict__ gW,
                    float* __restrict__ out)
{
    __shared__ uint32_t sA[64 * SA_STRIDE];   // 32 ap-diff rows + 32 an-diff rows (tf32)
    __shared__ uint32_t sB[KC * SB_STRIDE];   // W chunk [KC x 128] (tf32)
    __shared__ float    sD[64];               // per-diff-row squared norms

    const int t    = threadIdx.x;
    const int warp = t >> 5;
    const int lane = t & 31;
    const int warpM = warp & 1;   // 2 warps along M (32 diff rows each)
    const int warpN = warp >> 1;  // 4 warps along N (32 cols each)
    const int r0    = blockIdx.x * TM;

    // Accumulators: 2 m16-tiles x 4 n8-tiles x 4 regs = 32
    float acc[2][4][4];
#pragma unroll
    for (int mt = 0; mt < 2; ++mt)
#pragma unroll
        for (int nt = 0; nt < 4; ++nt)
#pragma unroll
            for (int i = 0; i < 4; ++i) acc[mt][nt][i] = 0.0f;

    // Per-thread gmem tile assignment
    // A/P/N: 32 rows x 8 float4 = 256 items -> 1 per thread
    // W:     32 rows x 32 float4 = 1024 items -> 4 per thread
    const int aRow = t >> 3;
    const int aC4  = t & 7;
    int wRow[4], wC4[4];
#pragma unroll
    for (int i = 0; i < 4; ++i) {
        int idx = i * 256 + t;
        wRow[i] = idx >> 5;
        wC4[i]  = idx & 31;
    }

    float4 ra, rp, rn, rw[4];

    // ---- prefetch chunk 0 ----
    {
        size_t off = (size_t)(r0 + aRow) * KDIM + aC4 * 4;
        ra = *(const float4*)(gA + off);
        rp = *(const float4*)(gP + off);
        rn = *(const float4*)(gN + off);
#pragma unroll
        for (int i = 0; i < 4; ++i) {
            size_t woff = (size_t)wRow[i] * NDIM + wC4[i] * 4;
            rw[i] = *(const float4*)(gW + woff);
        }
    }

#pragma unroll 1
    for (int c = 0; c < NCHUNK; ++c) {
        __syncthreads();   // previous chunk's compute done; smem free

        // store diffs (tf32, round-to-nearest) and W chunk (tf32) into smem
        {
            int col = aC4 * 4;
            uint32_t* ap = &sA[aRow * SA_STRIDE + col];
            uint32_t* an = &sA[(32 + aRow) * SA_STRIDE + col];
            ap[0] = f2tf32(ra.x - rp.x);
            ap[1] = f2tf32(ra.y - rp.y);
            ap[2] = f2tf32(ra.z - rp.z);
            ap[3] = f2tf32(ra.w - rp.w);
            an[0] = f2tf32(ra.x - rn.x);
            an[1] = f2tf32(ra.y - rn.y);
            an[2] = f2tf32(ra.z - rn.z);
            an[3] = f2tf32(ra.w - rn.w);
        }
#pragma unroll
        for (int i = 0; i < 4; ++i) {
            uint32_t* wp = &sB[wRow[i] * SB_STRIDE + wC4[i] * 4];
            wp[0] = f2tf32(rw[i].x);
            wp[1] = f2tf32(rw[i].y);
            wp[2] = f2tf32(rw[i].z);
            wp[3] = f2tf32(rw[i].w);
        }

        // prefetch next chunk while this one computes
        if (c + 1 < NCHUNK) {
            const int k0 = (c + 1) * KC;
            size_t off = (size_t)(r0 + aRow) * KDIM + k0 + aC4 * 4;
            ra = *(const float4*)(gA + off);
            rp = *(const float4*)(gP + off);
            rn = *(const float4*)(gN + off);
#pragma unroll
            for (int i = 0; i < 4; ++i) {
                size_t woff = (size_t)(k0 + wRow[i]) * NDIM + wC4[i] * 4;
                rw[i] = *(const float4*)(gW + woff);
            }
        }

        __syncthreads();   // smem tiles ready

        // compute: 4 k-substeps of 8
#pragma unroll
        for (int k8 = 0; k8 < 4; ++k8) {
            uint32_t af[2][4];
#pragma unroll
            for (int mt = 0; mt < 2; ++mt) {
                int row = warpM * 32 + mt * 16 + (lane >> 2);
                int col = k8 * 8 + (lane & 3);
                af[mt][0] = sA[row * SA_STRIDE + col];
                af[mt][1] = sA[(row + 8) * SA_STRIDE + col];
                af[mt][2] = sA[row * SA_STRIDE + col + 4];
                af[mt][3] = sA[(row + 8) * SA_STRIDE + col + 4];
            }
            uint32_t bf[4][2];
#pragma unroll
            for (int nt = 0; nt < 4; ++nt) {
                int ncol = warpN * 32 + nt * 8 + (lane >> 2);
                int krow = k8 * 8 + (lane & 3);
                bf[nt][0] = sB[krow * SB_STRIDE + ncol];
                bf[nt][1] = sB[(krow + 4) * SB_STRIDE + ncol];
            }
#pragma unroll
            for (int mt = 0; mt < 2; ++mt)
#pragma unroll
                for (int nt = 0; nt < 4; ++nt)
                    mma_tf32(acc[mt][nt], af[mt], bf[nt]);
        }
    }

    // ---- epilogue: per-row sum of squares over this warp's 32 N-cols ----
    __syncthreads();
    if (t < 64) sD[t] = 0.0f;
    __syncthreads();

#pragma unroll
    for (int mt = 0; mt < 2; ++mt) {
        int row = warpM * 32 + mt * 16 + (lane >> 2);
        float s0 = 0.0f, s1 = 0.0f;
#pragma unroll
        for (int nt = 0; nt < 4; ++nt) {
            s0 += acc[mt][nt][0] * acc[mt][nt][0] + acc[mt][nt][1] * acc[mt][nt][1];
            s1 += acc[mt][nt][2] * acc[mt][nt][2] + acc[mt][nt][3] * acc[mt][nt][3];
        }
        // reduce across the quad (lane&3 spans the 8 N-cols of each n-tile)
        s0 += __shfl_xor_sync(0xffffffff, s0, 1);
        s0 += __shfl_xor_sync(0xffffffff, s0, 2);
        s1 += __shfl_xor_sync(0xffffffff, s1, 1);
        s1 += __shfl_xor_sync(0xffffffff, s1, 2);
        if ((lane & 3) == 0) {
            atomicAdd(&sD[row], s0);        // 4 warpN warps contribute each row
            atomicAdd(&sD[row + 8], s1);
        }
    }
    __syncthreads();

    if (t < 32) {
        float d_ap = sD[t];
        float d_an = sD[32 + t];
        float loss = fmaxf(d_ap - d_an + ALPHA, 0.0f);
#pragma unroll
        for (int off = 16; off > 0; off >>= 1)
            loss += __shfl_xor_sync(0xffffffff, loss, off);
        if (t == 0)
            atomicAdd(out, loss * (1.0f / (float)B_ROWS));
    }
}

extern "C" void kernel_launch(void* const* d_in, const int* in_sizes, int n_in,
                              void* d_out, int out_size)
{
    const float* a = (const float*)d_in[0];  // batch_anchor [8192,1,48,48]
    const float* p = (const float*)d_in[1];  // batch_pos
    const float* n = (const float*)d_in[2];  // batch_neg
    const float* w = (const float*)d_in[3];  // W [2304,128]
    // d_in[4] = b, cancels in the differences; unused
    float* out = (float*)d_out;

    zero_out_kernel<<<1, 1>>>(out);
    triplet_kernel<<<B_ROWS / TM, 256>>>(a, p, n, w, out);
}

// round 11
// speedup vs baseline: 1.1809x; 1.1809x over previous
#include <cuda_runtime.h>
#include <cstdint>

// Problem constants
#define B_ROWS   8192
#define KDIM     2304     // 48*48
#define NDIM     128      // EMB_DIM
#define TM       64       // batch rows per CTA -> 128 diff rows (64 ap + 64 an)
#define KC       64       // K per chunk
#define NCHUNK   36       // 2304/64
#define ALPHA    0.2f
#define NTHREADS 512

// Padded smem strides (words). Chosen so MMA fragment loads are conflict-free:
//  A frag: bank=(68*row+col)%32 = (4*row+col)%32, row=lane>>2(0..7), col=lane&3 -> distinct
//  B frag: bank=(136*k+n)%32   = (8*k+n)%32,    k=lane&3, n=lane>>2(0..7)      -> distinct
#define SA_STRIDE 68      // KC + 4 pad
#define SB_STRIDE 136     // NDIM + 8 pad

// Dynamic smem layout (bytes)
#define SMA_BYTES (128 * SA_STRIDE * 4)       // 34816: 128 diff rows x KC
#define SMW_BYTES (KC * SB_STRIDE * 4)        // 34816: KC x 128 N
#define OFF_A(s)  ((s) * SMA_BYTES)
#define OFF_W(s)  (2 * SMA_BYTES + (s) * SMW_BYTES)
#define SMEM_DYN  (2 * SMA_BYTES + 2 * SMW_BYTES)   // 139264

// W pre-converted to tf32 (same [k][n] layout as source)
__device__ uint32_t g_wT[KDIM * NDIM];

// Round-to-nearest tf32. REQUIRED: HMMA-tf32 truncates raw fp32 mantissas and the
// truncation bias accumulates in the mean (measured 1.4e-3 rel_err without this).
__device__ __forceinline__ uint32_t f2tf32(float x) {
    uint32_t y; asm("cvt.rna.tf32.f32 %0, %1;" : "=r"(y) : "f"(x)); return y;
}

__device__ __forceinline__ void mma_tf32(float c[4], const uint32_t a[4], const uint32_t b[2]) {
    asm volatile(
        "mma.sync.aligned.m16n8k8.row.col.f32.tf32.tf32.f32 "
        "{%0,%1,%2,%3}, {%4,%5,%6,%7}, {%8,%9}, {%0,%1,%2,%3};"
        : "+f"(c[0]), "+f"(c[1]), "+f"(c[2]), "+f"(c[3])
        : "r"(a[0]), "r"(a[1]), "r"(a[2]), "r"(a[3]), "r"(b[0]), "r"(b[1]));
}

__device__ __forceinline__ uint32_t smem_u32(const void* p) {
    uint32_t a;
    asm("{ .reg .u64 t; cvta.to.shared.u64 t, %1; cvt.u32.u64 %0, t; }" : "=r"(a) : "l"(p));
    return a;
}
__device__ __forceinline__ void cp_async16(uint32_t dst, const void* src) {
    asm volatile("cp.async.cg.shared.global [%0], [%1], 16;" :: "r"(dst), "l"(src) : "memory");
}
#define CP_COMMIT() asm volatile("cp.async.commit_group;" ::: "memory")
#define CP_WAIT0()  asm volatile("cp.async.wait_group 0;" ::: "memory")

__global__ void zero_out_kernel(float* out) { out[0] = 0.0f; }

__global__ void prep_w_kernel(const float* __restrict__ gW) {
    int i = blockIdx.x * 256 + threadIdx.x;      // KDIM*NDIM = 294912 total
    g_wT[i] = f2tf32(gW[i]);
}

__global__ __launch_bounds__(NTHREADS, 1)
void triplet_kernel(const float* __restrict__ gA,
                    const float* __restrict__ gP,
                    const float* __restrict__ gN,
                    float* __restrict__ out)
{
    extern __shared__ char sm[];
    const uint32_t sb = smem_u32(sm);

    const int t     = threadIdx.x;
    const int warp  = t >> 5;
    const int lane  = t & 31;
    const int warpM = warp & 3;    // 4 warps along M: 32 diff rows each
    const int warpN = warp >> 2;   // 4 warps along N: 32 cols each
    const int r0    = blockIdx.x * TM;

    // Accumulators: 2 m16-tiles x 4 n8-tiles x 4 regs = 32
    float acc[2][4][4];
#pragma unroll
    for (int mt = 0; mt < 2; ++mt)
#pragma unroll
        for (int nt = 0; nt < 4; ++nt)
#pragma unroll
            for (int i = 0; i < 4; ++i) acc[mt][nt][i] = 0.0f;

    // A/P/N tile: 64 rows x 16 float4 (KC=64) = 1024 items -> 2 per thread
    int aRow[2], aC4[2];
#pragma unroll
    for (int i = 0; i < 2; ++i) {
        int idx = i * NTHREADS + t;
        aRow[i] = idx >> 4;
        aC4[i]  = idx & 15;
    }
    // W tile cp.async: 64 k-rows x 32 16B-segs = 2048 segs -> 4 per thread
    int wK[4], wSeg[4];
#pragma unroll
    for (int i = 0; i < 4; ++i) {
        int idx = i * NTHREADS + t;
        wK[i]   = idx >> 5;
        wSeg[i] = idx & 31;
    }

    float4 ra[2], rp[2], rn[2];

    // ---- prologue: prefetch A(0) regs; start W(0) cp.async ----
#pragma unroll
    for (int i = 0; i < 2; ++i) {
        size_t off = (size_t)(r0 + aRow[i]) * KDIM + aC4[i] * 4;
        ra[i] = *(const float4*)(gA + off);
        rp[i] = *(const float4*)(gP + off);
        rn[i] = *(const float4*)(gN + off);
    }
#pragma unroll
    for (int i = 0; i < 4; ++i)
        cp_async16(sb + OFF_W(0) + wK[i] * (SB_STRIDE * 4) + wSeg[i] * 16,
                   (const char*)g_wT + (size_t)wK[i] * (NDIM * 4) + wSeg[i] * 16);
    CP_COMMIT();

#pragma unroll 1
    for (int c = 0; c < NCHUNK; ++c) {
        const int s = c & 1;

        // A: STS diffs for chunk c (stage s free: compute(c-2) done before sync(c-1))
#pragma unroll
        for (int i = 0; i < 2; ++i) {
            uint4 ap, an;
            ap.x = f2tf32(ra[i].x - rp[i].x); ap.y = f2tf32(ra[i].y - rp[i].y);
            ap.z = f2tf32(ra[i].z - rp[i].z); ap.w = f2tf32(ra[i].w - rp[i].w);
            an.x = f2tf32(ra[i].x - rn[i].x); an.y = f2tf32(ra[i].y - rn[i].y);
            an.z = f2tf32(ra[i].z - rn[i].z); an.w = f2tf32(ra[i].w - rn[i].w);
            *(uint4*)(sm + OFF_A(s) + aRow[i] * (SA_STRIDE * 4) + aC4[i] * 16) = ap;
            *(uint4*)(sm + OFF_A(s) + (64 + aRow[i]) * (SA_STRIDE * 4) + aC4[i] * 16) = an;
        }

        // B: prefetch A(c+1) registers
        if (c + 1 < NCHUNK) {
#pragma unroll
            for (int i = 0; i < 2; ++i) {
                size_t off = (size_t)(r0 + aRow[i]) * KDIM + (c + 1) * KC + aC4[i] * 4;
                ra[i] = *(const float4*)(gA + off);
                rp[i] = *(const float4*)(gP + off);
                rn[i] = *(const float4*)(gN + off);
            }
        }

        // C: W(c) has landed; D: everyone's A(c) stores + W(c) visible
        CP_WAIT0();
        __syncthreads();

        // E: start W(c+1) into the stage vacated by compute(c-1) (all warps past sync)
        if (c + 1 < NCHUNK) {
            const char* wsrc = (const char*)g_wT + (size_t)(c + 1) * (KC * NDIM * 4);
#pragma unroll
            for (int i = 0; i < 4; ++i)
                cp_async16(sb + OFF_W(1 - s) + wK[i] * (SB_STRIDE * 4) + wSeg[i] * 16,
                           wsrc + (size_t)wK[i] * (NDIM * 4) + wSeg[i] * 16);
            CP_COMMIT();
        }

        // F: compute chunk c — 8 k8-substeps
        const uint32_t* sA = (const uint32_t*)(sm + OFF_A(s));
        const uint32_t* sW = (const uint32_t*)(sm + OFF_W(s));
#pragma unroll
        for (int k8 = 0; k8 < 8; ++k8) {
            uint32_t af[2][4];
#pragma unroll
            for (int mt = 0; mt < 2; ++mt) {
                int row = warpM * 32 + mt * 16 + (lane >> 2);
                int col = k8 * 8 + (lane & 3);
                af[mt][0] = sA[row * SA_STRIDE + col];
                af[mt][1] = sA[(row + 8) * SA_STRIDE + col];
                af[mt][2] = sA[row * SA_STRIDE + col + 4];
                af[mt][3] = sA[(row + 8) * SA_STRIDE + col + 4];
            }
            uint32_t bf[4][2];
#pragma unroll
            for (int nt = 0; nt < 4; ++nt) {
                int ncol = warpN * 32 + nt * 8 + (lane >> 2);
                int krow = k8 * 8 + (lane & 3);
                bf[nt][0] = sW[krow * SB_STRIDE + ncol];
                bf[nt][1] = sW[(krow + 4) * SB_STRIDE + ncol];
            }
#pragma unroll
            for (int mt = 0; mt < 2; ++mt)
#pragma unroll
                for (int nt = 0; nt < 4; ++nt)
                    mma_tf32(acc[mt][nt], af[mt], bf[nt]);
        }
    }

    // ---- epilogue: per-diff-row sum of squares ----
    __syncthreads();
    float* sD = (float*)sm;                 // reuse tile memory
    if (t < 128) sD[t] = 0.0f;
    __syncthreads();

#pragma unroll
    for (int mt = 0; mt < 2; ++mt) {
        int row = warpM * 32 + mt * 16 + (lane >> 2);
        float s0 = 0.0f, s1 = 0.0f;
#pragma unroll
        for (int nt = 0; nt < 4; ++nt) {
            s0 += acc[mt][nt][0] * acc[mt][nt][0] + acc[mt][nt][1] * acc[mt][nt][1];
            s1 += acc[mt][nt][2] * acc[mt][nt][2] + acc[mt][nt][3] * acc[mt][nt][3];
        }
        s0 += __shfl_xor_sync(0xffffffff, s0, 1);
        s0 += __shfl_xor_sync(0xffffffff, s0, 2);
        s1 += __shfl_xor_sync(0xffffffff, s1, 1);
        s1 += __shfl_xor_sync(0xffffffff, s1, 2);
        if ((lane & 3) == 0) {
            atomicAdd(&sD[row], s0);        // 4 warpN warps contribute per row
            atomicAdd(&sD[row + 8], s1);
        }
    }
    __syncthreads();

    if (t < 64) {
        float d_ap = sD[t];                 // rows 0..63  = ap diffs
        float d_an = sD[64 + t];            // rows 64..127 = an diffs
        float loss = fmaxf(d_ap - d_an + ALPHA, 0.0f);
#pragma unroll
        for (int off = 16; off > 0; off >>= 1)
            loss += __shfl_xor_sync(0xffffffff, loss, off);
        if ((t & 31) == 0)
            atomicAdd(out, loss * (1.0f / (float)B_ROWS));
    }
}

extern "C" void kernel_launch(void* const* d_in, const int* in_sizes, int n_in,
                              void* d_out, int out_size)
{
    const float* a = (const float*)d_in[0];  // batch_anchor [8192,1,48,48]
    const float* p = (const float*)d_in[1];  // batch_pos
    const float* n = (const float*)d_in[2];  // batch_neg
    const float* w = (const float*)d_in[3];  // W [2304,128]
    // d_in[4] = b: cancels in the differences; unused
    float* out = (float*)d_out;

    static bool attr_set = false;
    if (!attr_set) {
        cudaFuncSetAttribute(triplet_kernel,
                             cudaFuncAttributeMaxDynamicSharedMemorySize, SMEM_DYN);
        attr_set = true;
    }

    zero_out_kernel<<<1, 1>>>(out);
    prep_w_kernel<<<(KDIM * NDIM) / 256, 256>>>(w);
    triplet_kernel<<<B_ROWS / TM, NTHREADS, SMEM_DYN>>>(a, p, n, out);
}

// round 15
// speedup vs baseline: 1.8348x; 1.5538x over previous
#include <cuda_runtime.h>
#include <cuda_bf16.h>
#include <cstdint>

// Problem constants
#define B_ROWS   8192
#define KDIM     2304     // 48*48
#define NDIM     128      // EMB_DIM
#define TM       64       // batch rows per CTA -> 128 diff rows (64 ap + 64 an)
#define KC       64       // K per chunk
#define NCHUNK   36       // 2304/64
#define ALPHA    0.2f
#define NTHREADS 512

// Strides in 32-bit words (bf16x2 units). Row = 64 bf16 data + 8 bf16 pad = 36 words.
// Fragment-load banks: A: (36*row + kp)%32 = 4*row + kp, row=lane>>2, kp=lane&3 -> 32 distinct.
//                      B: 4*ncol + kp with ncol spanning lane>>2 -> 32 distinct.
#define SA_W 36
#define SW_W 36

// Dynamic smem layout (bytes)
#define SMA_BYTES (128 * SA_W * 4)        // 18432: 128 diff rows x (KC bf16 + pad)
#define SMW_BYTES (128 * SW_W * 4)        // 18432: 128 n-rows x (KC bf16 + pad)
#define OFF_A(s)  ((s) * SMA_BYTES)
#define OFF_W(s)  (2 * SMA_BYTES + (s) * SMW_BYTES)
#define SMEM_DYN  (2 * SMA_BYTES + 2 * SMW_BYTES)   // 73728

// W transposed to [n][k], bf16 (round-to-nearest)
__device__ __nv_bfloat16 g_wT[(size_t)NDIM * KDIM];

// Pack two floats to bf16x2 (lo = first, hi = second), round-to-nearest (unbiased).
__device__ __forceinline__ uint32_t pack_bf16x2(float lo, float hi) {
    uint32_t r;
    asm("cvt.rn.bf16x2.f32 %0, %1, %2;" : "=r"(r) : "f"(hi), "f"(lo));
    return r;
}

__device__ __forceinline__ void mma_bf16(float c[4], const uint32_t a[4], const uint32_t b[2]) {
    asm volatile(
        "mma.sync.aligned.m16n8k16.row.col.f32.bf16.bf16.f32 "
        "{%0,%1,%2,%3}, {%4,%5,%6,%7}, {%8,%9}, {%0,%1,%2,%3};"
        : "+f"(c[0]), "+f"(c[1]), "+f"(c[2]), "+f"(c[3])
        : "r"(a[0]), "r"(a[1]), "r"(a[2]), "r"(a[3]), "r"(b[0]), "r"(b[1]));
}

__device__ __forceinline__ uint32_t smem_u32(const void* p) {
    uint32_t a;
    asm("{ .reg .u64 t; cvta.to.shared.u64 t, %1; cvt.u32.u64 %0, t; }" : "=r"(a) : "l"(p));
    return a;
}
__device__ __forceinline__ void cp_async16(uint32_t dst, const void* src) {
    asm volatile("cp.async.cg.shared.global [%0], [%1], 16;" :: "r"(dst), "l"(src) : "memory");
}
#define CP_COMMIT() asm volatile("cp.async.commit_group;" ::: "memory")
#define CP_WAIT0()  asm volatile("cp.async.wait_group 0;" ::: "memory")

// prep: W [k][n] fp32 -> g_wT [n][k] bf16; thread 0 also zeroes the output scalar.
__global__ void prep_w_kernel(const float* __restrict__ gW, float* __restrict__ out) {
    int i = blockIdx.x * 256 + threadIdx.x;          // over NDIM*KDIM = 294912
    if (i == 0) out[0] = 0.0f;
    int n = i / KDIM;
    int k = i - n * KDIM;
    g_wT[i] = __float2bfloat16_rn(gW[(size_t)k * NDIM + n]);   // write coalesced in k
}

__global__ __launch_bounds__(NTHREADS, 1)
void triplet_kernel(const float* __restrict__ gA,
                    const float* __restrict__ gP,
                    const float* __restrict__ gN,
                    float* __restrict__ out)
{
    extern __shared__ char sm[];
    const uint32_t sb = smem_u32(sm);

    const int t     = threadIdx.x;
    const int warp  = t >> 5;
    const int lane  = t & 31;
    const int warpM = warp & 3;    // 4 warps along M: 32 diff rows each
    const int warpN = warp >> 2;   // 4 warps along N: 32 cols each
    const int r0    = blockIdx.x * TM;

    // Accumulators: 2 m16-tiles x 4 n8-tiles x 4 regs = 32
    float acc[2][4][4];
#pragma unroll
    for (int mt = 0; mt < 2; ++mt)
#pragma unroll
        for (int nt = 0; nt < 4; ++nt)
#pragma unroll
            for (int i = 0; i < 4; ++i) acc[mt][nt][i] = 0.0f;

    // A/P/N tile: 64 rows x 16 float4 (KC=64) = 1024 items -> 2 per thread
    int aRow[2], aC4[2];
#pragma unroll
    for (int i = 0; i < 2; ++i) {
        int idx = i * NTHREADS + t;
        aRow[i] = idx >> 4;
        aC4[i]  = idx & 15;
    }
    // W tile cp.async: 128 n-rows x 8 16B-segs = 1024 -> 2 per thread
    int wN[2], wSeg[2];
#pragma unroll
    for (int i = 0; i < 2; ++i) {
        int idx = i * NTHREADS + t;
        wN[i]   = idx >> 3;
        wSeg[i] = idx & 7;
    }

    float4 ra[2], rp[2], rn[2];

    // ---- prologue: prefetch A(0) regs; start W(0) cp.async ----
#pragma unroll
    for (int i = 0; i < 2; ++i) {
        size_t off = (size_t)(r0 + aRow[i]) * KDIM + aC4[i] * 4;
        ra[i] = *(const float4*)(gA + off);
        rp[i] = *(const float4*)(gP + off);
        rn[i] = *(const float4*)(gN + off);
    }
#pragma unroll
    for (int i = 0; i < 2; ++i)
        cp_async16(sb + OFF_W(0) + wN[i] * (SW_W * 4) + wSeg[i] * 16,
                   (const char*)g_wT + (size_t)wN[i] * (KDIM * 2) + wSeg[i] * 16);
    CP_COMMIT();

#pragma unroll 1
    for (int c = 0; c < NCHUNK; ++c) {
        const int s = c & 1;

        // A: STS bf16x2 diffs for chunk c (stage s free: compute(c-2) done before sync(c-1))
#pragma unroll
        for (int i = 0; i < 2; ++i) {
            uint2 ap, an;
            ap.x = pack_bf16x2(ra[i].x - rp[i].x, ra[i].y - rp[i].y);
            ap.y = pack_bf16x2(ra[i].z - rp[i].z, ra[i].w - rp[i].w);
            an.x = pack_bf16x2(ra[i].x - rn[i].x, ra[i].y - rn[i].y);
            an.y = pack_bf16x2(ra[i].z - rn[i].z, ra[i].w - rn[i].w);
            *(uint2*)(sm + OFF_A(s) + aRow[i] * (SA_W * 4) + aC4[i] * 8) = ap;
            *(uint2*)(sm + OFF_A(s) + (64 + aRow[i]) * (SA_W * 4) + aC4[i] * 8) = an;
        }

        // B: prefetch A(c+1) registers
        if (c + 1 < NCHUNK) {
#pragma unroll
            for (int i = 0; i < 2; ++i) {
                size_t off = (size_t)(r0 + aRow[i]) * KDIM + (c + 1) * KC + aC4[i] * 4;
                ra[i] = *(const float4*)(gA + off);
                rp[i] = *(const float4*)(gP + off);
                rn[i] = *(const float4*)(gN + off);
            }
        }

        // C: W(c) landed; D: all A(c) stores + W(c) visible to all warps
        CP_WAIT0();
        __syncthreads();

        // E: start W(c+1) into the stage vacated by compute(c-1)
        if (c + 1 < NCHUNK) {
            const char* wsrc = (const char*)g_wT + (size_t)(c + 1) * (KC * 2);
#pragma unroll
            for (int i = 0; i < 2; ++i)
                cp_async16(sb + OFF_W(1 - s) + wN[i] * (SW_W * 4) + wSeg[i] * 16,
                           wsrc + (size_t)wN[i] * (KDIM * 2) + wSeg[i] * 16);
            CP_COMMIT();
        }

        // F: compute chunk c — 4 k16-substeps (KC=64)
        const uint32_t* sA = (const uint32_t*)(sm + OFF_A(s));
        const uint32_t* sW = (const uint32_t*)(sm + OFF_W(s));
#pragma unroll
        for (int k16 = 0; k16 < 4; ++k16) {
            const int kp = k16 * 8 + (lane & 3);     // bf16x2 word index within row
            uint32_t af[2][4];
#pragma unroll
            for (int mt = 0; mt < 2; ++mt) {
                int row = warpM * 32 + mt * 16 + (lane >> 2);
                af[mt][0] = sA[row * SA_W + kp];
                af[mt][1] = sA[(row + 8) * SA_W + kp];
                af[mt][2] = sA[row * SA_W + kp + 4];
                af[mt][3] = sA[(row + 8) * SA_W + kp + 4];
            }
            uint32_t bf[4][2];
#pragma unroll
            for (int nt = 0; nt < 4; ++nt) {
                int ncol = warpN * 32 + nt * 8 + (lane >> 2);
                bf[nt][0] = sW[ncol * SW_W + kp];
                bf[nt][1] = sW[ncol * SW_W + kp + 4];
            }
#pragma unroll
            for (int mt = 0; mt < 2; ++mt)
#pragma unroll
                for (int nt = 0; nt < 4; ++nt)
                    mma_bf16(acc[mt][nt], af[mt], bf[nt]);
        }
    }

    // ---- epilogue: per-diff-row sum of squares ----
    __syncthreads();
    float* sD = (float*)sm;                 // reuse tile memory
    if (t < 128) sD[t] = 0.0f;
    __syncthreads();

#pragma unroll
    for (int mt = 0; mt < 2; ++mt) {
        int row = warpM * 32 + mt * 16 + (lane >> 2);
        float s0 = 0.0f, s1 = 0.0f;
#pragma unroll
        for (int nt = 0; nt < 4; ++nt) {
            s0 += acc[mt][nt][0] * acc[mt][nt][0] + acc[mt][nt][1] * acc[mt][nt][1];
            s1 += acc[mt][nt][2] * acc[mt][nt][2] + acc[mt][nt][3] * acc[mt][nt][3];
        }
        s0 += __shfl_xor_sync(0xffffffff, s0, 1);
        s0 += __shfl_xor_sync(0xffffffff, s0, 2);
        s1 += __shfl_xor_sync(0xffffffff, s1, 1);
        s1 += __shfl_xor_sync(0xffffffff, s1, 2);
        if ((lane & 3) == 0) {
            atomicAdd(&sD[row], s0);        // 4 warpN warps contribute per row
            atomicAdd(&sD[row + 8], s1);
        }
    }
    __syncthreads();

    if (t < 64) {
        float d_ap = sD[t];                 // rows 0..63   = ap diffs
        float d_an = sD[64 + t];            // rows 64..127 = an diffs
        float loss = fmaxf(d_ap - d_an + ALPHA, 0.0f);
#pragma unroll
        for (int off = 16; off > 0; off >>= 1)
            loss += __shfl_xor_sync(0xffffffff, loss, off);
        if ((t & 31) == 0)
            atomicAdd(out, loss * (1.0f / (float)B_ROWS));
    }
}

extern "C" void kernel_launch(void* const* d_in, const int* in_sizes, int n_in,
                              void* d_out, int out_size)
{
    const float* a = (const float*)d_in[0];  // batch_anchor [8192,1,48,48]
    const float* p = (const float*)d_in[1];  // batch_pos
    const float* n = (const float*)d_in[2];  // batch_neg
    const float* w = (const float*)d_in[3];  // W [2304,128]
    // d_in[4] = b: cancels in the differences; unused
    float* out = (float*)d_out;

    static bool attr_set = false;
    if (!attr_set) {
        cudaFuncSetAttribute(triplet_kernel,
                             cudaFuncAttributeMaxDynamicSharedMemorySize, SMEM_DYN);
        attr_set = true;
    }

    prep_w_kernel<<<(NDIM * KDIM) / 256, 256>>>(w, out);   // also zeroes out[0]
    triplet_kernel<<<B_ROWS / TM, NTHREADS, SMEM_DYN>>>(a, p, n, out);
}